// round 1
// baseline (speedup 1.0000x reference)
#include <cuda_runtime.h>
#include <cmath>

#define BATCH 8
#define SEQ   2048
#define DIM   512
#define MROWS (BATCH * SEQ)   // 16384

// Scratch for Q, K, V projections (allocation-free: __device__ globals)
__device__ float g_Q[MROWS * DIM];
__device__ float g_K[MROWS * DIM];
__device__ float g_V[MROWS * DIM];

// ---------------- GEMM tiling parameters ----------------
#define BM 128
#define BN 128
#define BK 16
#define TM 8
#define TN 8
// 256 threads per block: 16x16 thread grid of 8x8 register tiles

// ============================================================
// Kernel 1: QKV projection.  out = X @ W^T + b   (NT GEMM)
// X: [MROWS, DIM] row-major.  W: [DIM, DIM] row-major (out,in).
// blockIdx.z in {0,1,2} selects {Q,K,V}.
// ============================================================
__global__ __launch_bounds__(256) void qkv_kernel(
    const float* __restrict__ X,
    const float* __restrict__ Wq, const float* __restrict__ bq,
    const float* __restrict__ Wk, const float* __restrict__ bk,
    const float* __restrict__ Wv, const float* __restrict__ bv)
{
    const float* W;
    const float* bias;
    float* out;
    if (blockIdx.z == 0)      { W = Wq; bias = bq; out = g_Q; }
    else if (blockIdx.z == 1) { W = Wk; bias = bk; out = g_K; }
    else                      { W = Wv; bias = bv; out = g_V; }

    __shared__ float As[BK][BM];
    __shared__ float Bs[BK][BN];

    const int tid = threadIdx.x;
    const int m0 = blockIdx.y * BM;
    const int n0 = blockIdx.x * BN;
    const int tr = tid >> 4;   // 0..15
    const int tc = tid & 15;   // 0..15

    float acc[TM][TN] = {};

    for (int kt = 0; kt < DIM; kt += BK) {
        // Load A tile: 128 rows x 16 k = 512 float4, 2 per thread
        #pragma unroll
        for (int i = 0; i < 2; i++) {
            int l = tid + i * 256;
            int row = l >> 2;
            int c4 = (l & 3) * 4;
            float4 v = *(const float4*)&X[(size_t)(m0 + row) * DIM + kt + c4];
            As[c4 + 0][row] = v.x; As[c4 + 1][row] = v.y;
            As[c4 + 2][row] = v.z; As[c4 + 3][row] = v.w;
        }
        // Load B tile (rows of W, NT): 128 rows x 16 k
        #pragma unroll
        for (int i = 0; i < 2; i++) {
            int l = tid + i * 256;
            int row = l >> 2;
            int c4 = (l & 3) * 4;
            float4 v = *(const float4*)&W[(size_t)(n0 + row) * DIM + kt + c4];
            Bs[c4 + 0][row] = v.x; Bs[c4 + 1][row] = v.y;
            Bs[c4 + 2][row] = v.z; Bs[c4 + 3][row] = v.w;
        }
        __syncthreads();

        #pragma unroll
        for (int k = 0; k < BK; k++) {
            float ra[TM], rb[TN];
            #pragma unroll
            for (int i = 0; i < TM; i++) ra[i] = As[k][tr * TM + i];
            #pragma unroll
            for (int j = 0; j < TN; j++) rb[j] = Bs[k][tc * TN + j];
            #pragma unroll
            for (int i = 0; i < TM; i++)
                #pragma unroll
                for (int j = 0; j < TN; j++)
                    acc[i][j] = fmaf(ra[i], rb[j], acc[i][j]);
        }
        __syncthreads();
    }

    #pragma unroll
    for (int i = 0; i < TM; i++) {
        int m = m0 + tr * TM + i;
        #pragma unroll
        for (int j = 0; j < TN; j++) {
            int n = n0 + tc * TN + j;
            out[(size_t)m * DIM + n] = acc[i][j] + bias[n];
        }
    }
}

// ============================================================
// Kernel 2: scores = Q @ K^T / sqrt(D), masked.  (NT GEMM per batch)
// Writes raw masked scores into the weights region of d_out.
// ============================================================
__global__ __launch_bounds__(256) void scores_kernel(
    const int* __restrict__ mask, float* __restrict__ out_w, float scale)
{
    const int b = blockIdx.z;
    const float* Q = g_Q + (size_t)b * SEQ * DIM;
    const float* K = g_K + (size_t)b * SEQ * DIM;

    __shared__ float As[BK][BM];
    __shared__ float Bs[BK][BN];

    const int tid = threadIdx.x;
    const int m0 = blockIdx.y * BM;
    const int n0 = blockIdx.x * BN;
    const int tr = tid >> 4;
    const int tc = tid & 15;

    float acc[TM][TN] = {};

    for (int kt = 0; kt < DIM; kt += BK) {
        #pragma unroll
        for (int i = 0; i < 2; i++) {
            int l = tid + i * 256;
            int row = l >> 2;
            int c4 = (l & 3) * 4;
            float4 v = *(const float4*)&Q[(size_t)(m0 + row) * DIM + kt + c4];
            As[c4 + 0][row] = v.x; As[c4 + 1][row] = v.y;
            As[c4 + 2][row] = v.z; As[c4 + 3][row] = v.w;
        }
        #pragma unroll
        for (int i = 0; i < 2; i++) {
            int l = tid + i * 256;
            int row = l >> 2;
            int c4 = (l & 3) * 4;
            float4 v = *(const float4*)&K[(size_t)(n0 + row) * DIM + kt + c4];
            Bs[c4 + 0][row] = v.x; Bs[c4 + 1][row] = v.y;
            Bs[c4 + 2][row] = v.z; Bs[c4 + 3][row] = v.w;
        }
        __syncthreads();

        #pragma unroll
        for (int k = 0; k < BK; k++) {
            float ra[TM], rb[TN];
            #pragma unroll
            for (int i = 0; i < TM; i++) ra[i] = As[k][tr * TM + i];
            #pragma unroll
            for (int j = 0; j < TN; j++) rb[j] = Bs[k][tc * TN + j];
            #pragma unroll
            for (int i = 0; i < TM; i++)
                #pragma unroll
                for (int j = 0; j < TN; j++)
                    acc[i][j] = fmaf(ra[i], rb[j], acc[i][j]);
        }
        __syncthreads();
    }

    const size_t base = (size_t)b * SEQ * SEQ;
    #pragma unroll
    for (int i = 0; i < TM; i++) {
        int m = m0 + tr * TM + i;
        #pragma unroll
        for (int j = 0; j < TN; j++) {
            int n = n0 + tc * TN + j;
            float v = acc[i][j] * scale;
            int mk = mask[base + (size_t)m * SEQ + n];
            if (mk == 0) v = -1e9f;
            out_w[base + (size_t)m * SEQ + n] = v;
        }
    }
}

// ============================================================
// Kernel 3: in-place row softmax over the last dim (2048).
// One block (256 threads) per row; 8 elements per thread.
// ============================================================
__global__ __launch_bounds__(256) void softmax_kernel(float* __restrict__ W)
{
    float* p = W + (size_t)blockIdx.x * SEQ;
    const int tid = threadIdx.x;

    float vals[8];
    float m = -INFINITY;
    #pragma unroll
    for (int i = 0; i < 8; i++) {
        vals[i] = p[tid + i * 256];
        m = fmaxf(m, vals[i]);
    }

    __shared__ float red[256];
    red[tid] = m;
    __syncthreads();
    #pragma unroll
    for (int s = 128; s > 0; s >>= 1) {
        if (tid < s) red[tid] = fmaxf(red[tid], red[tid + s]);
        __syncthreads();
    }
    m = red[0];
    __syncthreads();

    float sum = 0.0f;
    #pragma unroll
    for (int i = 0; i < 8; i++) {
        vals[i] = __expf(vals[i] - m);
        sum += vals[i];
    }
    red[tid] = sum;
    __syncthreads();
    #pragma unroll
    for (int s = 128; s > 0; s >>= 1) {
        if (tid < s) red[tid] += red[tid + s];
        __syncthreads();
    }
    float inv = 1.0f / red[0];

    #pragma unroll
    for (int i = 0; i < 8; i++)
        p[tid + i * 256] = vals[i] * inv;
}

// ============================================================
// Kernel 4: O = weights @ V   (NN GEMM per batch)
// weights: [SEQ, SEQ] row-major,  V: [SEQ, DIM] row-major.
// ============================================================
__global__ __launch_bounds__(256) void out_kernel(
    const float* __restrict__ Wgt, float* __restrict__ O)
{
    const int b = blockIdx.z;
    const float* A = Wgt + (size_t)b * SEQ * SEQ;
    const float* V = g_V + (size_t)b * SEQ * DIM;
    float* out = O + (size_t)b * SEQ * DIM;

    __shared__ float As[BK][BM];
    __shared__ float Bs[BK][BN];

    const int tid = threadIdx.x;
    const int m0 = blockIdx.y * BM;
    const int n0 = blockIdx.x * BN;
    const int tr = tid >> 4;
    const int tc = tid & 15;

    float acc[TM][TN] = {};

    for (int kt = 0; kt < SEQ; kt += BK) {
        // A tile: 128 rows x 16 k (row-major, K-contiguous)
        #pragma unroll
        for (int i = 0; i < 2; i++) {
            int l = tid + i * 256;
            int row = l >> 2;
            int c4 = (l & 3) * 4;
            float4 v = *(const float4*)&A[(size_t)(m0 + row) * SEQ + kt + c4];
            As[c4 + 0][row] = v.x; As[c4 + 1][row] = v.y;
            As[c4 + 2][row] = v.z; As[c4 + 3][row] = v.w;
        }
        // B tile: 16 k-rows x 128 n-cols (NN: V row-major, N-contiguous)
        #pragma unroll
        for (int i = 0; i < 2; i++) {
            int l = tid + i * 256;
            int row = l >> 5;          // /32 -> 0..15
            int c4 = (l & 31) * 4;     // 0..124
            float4 v = *(const float4*)&V[(size_t)(kt + row) * DIM + n0 + c4];
            Bs[row][c4 + 0] = v.x; Bs[row][c4 + 1] = v.y;
            Bs[row][c4 + 2] = v.z; Bs[row][c4 + 3] = v.w;
        }
        __syncthreads();

        #pragma unroll
        for (int k = 0; k < BK; k++) {
            float ra[TM], rb[TN];
            #pragma unroll
            for (int i = 0; i < TM; i++) ra[i] = As[k][tr * TM + i];
            #pragma unroll
            for (int j = 0; j < TN; j++) rb[j] = Bs[k][tc * TN + j];
            #pragma unroll
            for (int i = 0; i < TM; i++)
                #pragma unroll
                for (int j = 0; j < TN; j++)
                    acc[i][j] = fmaf(ra[i], rb[j], acc[i][j]);
        }
        __syncthreads();
    }

    #pragma unroll
    for (int i = 0; i < TM; i++) {
        int m = m0 + tr * TM + i;
        #pragma unroll
        for (int j = 0; j < TN; j++) {
            int n = n0 + tc * TN + j;
            out[(size_t)m * DIM + n] = acc[i][j];
        }
    }
}

// ============================================================
extern "C" void kernel_launch(void* const* d_in, const int* in_sizes, int n_in,
                              void* d_out, int out_size)
{
    const float* X  = (const float*)d_in[0];
    const int*   mk = (const int*)  d_in[1];
    const float* Wq = (const float*)d_in[2];
    const float* bq = (const float*)d_in[3];
    const float* Wk = (const float*)d_in[4];
    const float* bk = (const float*)d_in[5];
    const float* Wv = (const float*)d_in[6];
    const float* bv = (const float*)d_in[7];

    float* out   = (float*)d_out;
    float* out_S = out;                                  // [B, S, D]
    float* out_W = out + (size_t)BATCH * SEQ * DIM;      // [B, S, S]

    const float scale = 1.0f / sqrtf((float)DIM);

    // 1) QKV projections
    {
        dim3 grid(DIM / BN, MROWS / BM, 3);
        qkv_kernel<<<grid, 256>>>(X, Wq, bq, Wk, bk, Wv, bv);
    }
    // 2) masked scores -> weights buffer
    {
        dim3 grid(SEQ / BN, SEQ / BM, BATCH);
        scores_kernel<<<grid, 256>>>(mk, out_W, scale);
    }
    // 3) softmax in place
    {
        softmax_kernel<<<BATCH * SEQ, 256>>>(out_W);
    }
    // 4) O = weights @ V
    {
        dim3 grid(DIM / BN, SEQ / BM, BATCH);
        out_kernel<<<grid, 256>>>(out_W, out_S);
    }
}

// round 3
// speedup vs baseline: 1.4211x; 1.4211x over previous
#include <cuda_runtime.h>
#include <cstdint>
#include <cmath>

#define BATCH 8
#define SEQ   2048
#define DIM   512
#define MROWS (BATCH * SEQ)   // 16384

// -------- scratch (allocation-free) --------
__device__ float g_Q[MROWS * DIM];           // [t][e]
__device__ float g_K[MROWS * DIM];           // [t][e]
__device__ float g_Vt[BATCH * DIM * SEQ];    // [b][d][s]  (V transposed)

// -------- tiling --------
#define BK 32
#define STAGES 4
#define TILE_BYTES  (128 * BK * 4)          // 16 KB (128 rows x 32 fp32)
#define STAGE_BYTES (2 * TILE_BYTES)        // A + B
#define SMEM_BYTES  (STAGES * STAGE_BYTES)  // 128 KB

// ================= PTX helpers =================
__device__ __forceinline__ uint32_t smem_u32(const void* p) {
    uint32_t a;
    asm("{ .reg .u64 t; cvta.to.shared.u64 t, %1; cvt.u32.u64 %0, t; }" : "=r"(a) : "l"(p));
    return a;
}
__device__ __forceinline__ void cp16(uint32_t dst, const void* src) {
    asm volatile("cp.async.cg.shared.global [%0], [%1], 16;" :: "r"(dst), "l"(src));
}
#define CP_COMMIT() asm volatile("cp.async.commit_group;" ::: "memory")
#define CP_WAIT2()  asm volatile("cp.async.wait_group 2;" ::: "memory")

__device__ __forceinline__ uint32_t cvt_tf32(float x) {
    uint32_t u; asm("cvt.rna.tf32.f32 %0, %1;" : "=r"(u) : "f"(x)); return u;
}
__device__ __forceinline__ float lds_f(uint32_t addr) {
    float v; asm volatile("ld.shared.f32 %0, [%1];" : "=f"(v) : "r"(addr)); return v;
}
__device__ __forceinline__ void mma8(float* d, const uint32_t* a, const uint32_t* b) {
    asm volatile("mma.sync.aligned.m16n8k8.row.col.f32.tf32.tf32.f32 "
        "{%0,%1,%2,%3}, {%4,%5,%6,%7}, {%8,%9}, {%0,%1,%2,%3};"
        : "+f"(d[0]), "+f"(d[1]), "+f"(d[2]), "+f"(d[3])
        : "r"(a[0]), "r"(a[1]), "r"(a[2]), "r"(a[3]), "r"(b[0]), "r"(b[1]));
}

// Load a 128x32 fp32 tile into smem with the (c + 4*row)&31 float swizzle.
// Swizzle keeps each 16B chunk contiguous: chunk c4 of row r lands at
// bytes r*128 + ((c4 + r)&7)*16.
__device__ __forceinline__ void load_tile(uint32_t sdst, const float* __restrict__ src,
                                          int ld, int tid)
{
    #pragma unroll
    for (int i = 0; i < 4; i++) {
        int row = (tid >> 3) + i * 32;
        int c4  = tid & 7;
        uint32_t doff = (uint32_t)(row * 128 + (((c4 + row) & 7) << 4));
        cp16(sdst + doff, src + (size_t)row * ld + c4 * 4);
    }
}

// ================= GEMM mainloop =================
// acc[mt][nt][4] = A(128 x ktot) * B(128 x ktot)^T tile, 3xTF32 split.
// 8 warps: warpM = wid&3 (32 rows), warpN = wid>>2 (64 cols).
__device__ __forceinline__ void gemm_main(
    const float* __restrict__ A, int lda,
    const float* __restrict__ B, int ldb,
    int ktot, float (&acc)[2][8][4], char* smem, int tid)
{
    const int wid = tid >> 5, lane = tid & 31;
    const int wm = (wid & 3) * 32, wn = (wid >> 2) * 64;
    const int g = lane >> 2, tg = lane & 3;
    const uint32_t sbase = smem_u32(smem);
    const int NK = ktot / BK;

    int pf = 0;
    #pragma unroll
    for (int s = 0; s < STAGES - 1; s++) {
        if (pf < NK) {
            uint32_t sp = sbase + (uint32_t)(pf & (STAGES - 1)) * STAGE_BYTES;
            load_tile(sp, A + pf * BK, lda, tid);
            load_tile(sp + TILE_BYTES, B + pf * BK, ldb, tid);
            CP_COMMIT();
            pf++;
        }
    }

    for (int kb = 0; kb < NK; kb++) {
        CP_WAIT2();
        __syncthreads();
        const uint32_t sa = sbase + (uint32_t)(kb & (STAGES - 1)) * STAGE_BYTES;
        const uint32_t sb = sa + TILE_BYTES;

        if (pf < NK) {
            uint32_t sp = sbase + (uint32_t)(pf & (STAGES - 1)) * STAGE_BYTES;
            load_tile(sp, A + pf * BK, lda, tid);
            load_tile(sp + TILE_BYTES, B + pf * BK, ldb, tid);
            CP_COMMIT();
            pf++;
        }

        #pragma unroll
        for (int ks = 0; ks < 4; ks++) {
            // ---- A fragments (2 m-tiles), split hi/lo ----
            uint32_t ahi[2][4], alo[2][4];
            #pragma unroll
            for (int mt = 0; mt < 2; mt++) {
                #pragma unroll
                for (int cc = 0; cc < 2; cc++) {
                    #pragma unroll
                    for (int h = 0; h < 2; h++) {
                        int r = wm + mt * 16 + h * 8 + g;
                        int c = ks * 8 + cc * 4 + tg;
                        float v = lds_f(sa + (uint32_t)(r * 128 + (((c + 4 * r) & 31) << 2)));
                        uint32_t hi = cvt_tf32(v);
                        int id = h + 2 * cc;
                        ahi[mt][id] = hi;
                        alo[mt][id] = cvt_tf32(v - __uint_as_float(hi));
                    }
                }
            }
            // ---- B fragments in 2 halves of 4 n-tiles ----
            #pragma unroll
            for (int nh = 0; nh < 2; nh++) {
                uint32_t bhi[4][2], blo[4][2];
                #pragma unroll
                for (int nt = 0; nt < 4; nt++) {
                    #pragma unroll
                    for (int kk = 0; kk < 2; kk++) {
                        int n = wn + nh * 32 + nt * 8 + g;
                        int c = ks * 8 + kk * 4 + tg;
                        float v = lds_f(sb + (uint32_t)(n * 128 + (((c + 4 * n) & 31) << 2)));
                        uint32_t hi = cvt_tf32(v);
                        bhi[nt][kk] = hi;
                        blo[nt][kk] = cvt_tf32(v - __uint_as_float(hi));
                    }
                }
                #pragma unroll
                for (int mt = 0; mt < 2; mt++)
                    #pragma unroll
                    for (int nt = 0; nt < 4; nt++)
                        mma8(acc[mt][nh * 4 + nt], ahi[mt], bhi[nt]);
                #pragma unroll
                for (int mt = 0; mt < 2; mt++)
                    #pragma unroll
                    for (int nt = 0; nt < 4; nt++)
                        mma8(acc[mt][nh * 4 + nt], ahi[mt], blo[nt]);
                #pragma unroll
                for (int mt = 0; mt < 2; mt++)
                    #pragma unroll
                    for (int nt = 0; nt < 4; nt++)
                        mma8(acc[mt][nh * 4 + nt], alo[mt], bhi[nt]);
            }
        }
    }
}

// Epilogue index helpers: for (mt, nt, half h):
//   m = m0 + wm + mt*16 + g (+8 for regs c2,c3)
//   n = n0 + wn + nt*8 + tg*2
// ================= kernels =================

// Q/K projection: C[t][e] = X[t]·W[e];  out[t*DIM+e] + bias[e]
__global__ __launch_bounds__(256, 1) void qk_proj_kernel(
    const float* __restrict__ X,
    const float* __restrict__ Wq, const float* __restrict__ bq,
    const float* __restrict__ Wk, const float* __restrict__ bk)
{
    extern __shared__ char smem[];
    const int tid = threadIdx.x, wid = tid >> 5, lane = tid & 31;
    const int g = lane >> 2, tg = lane & 3;
    const int m0 = blockIdx.y * 128, n0 = blockIdx.x * 128;
    const float* W    = blockIdx.z ? Wk : Wq;
    const float* bias = blockIdx.z ? bk : bq;
    float* out        = blockIdx.z ? g_K : g_Q;

    float acc[2][8][4] = {};
    gemm_main(X + (size_t)m0 * DIM, DIM, W + (size_t)n0 * DIM, DIM, DIM, acc, smem, tid);

    const int wm = (wid & 3) * 32, wn = (wid >> 2) * 64;
    #pragma unroll
    for (int mt = 0; mt < 2; mt++) {
        int m = m0 + wm + mt * 16 + g;
        #pragma unroll
        for (int nt = 0; nt < 8; nt++) {
            int n = n0 + wn + nt * 8 + tg * 2;
            float b0 = bias[n], b1 = bias[n + 1];
            float2 v0 = make_float2(acc[mt][nt][0] + b0, acc[mt][nt][1] + b1);
            float2 v1 = make_float2(acc[mt][nt][2] + b0, acc[mt][nt][3] + b1);
            *(float2*)&out[(size_t)m * DIM + n] = v0;
            *(float2*)&out[(size_t)(m + 8) * DIM + n] = v1;
        }
    }
}

// V projection transposed: C[e][t] = Wv[e]·X[t]; g_Vt[(b*DIM+e)*SEQ+s] + bv[e]
__global__ __launch_bounds__(256, 1) void v_proj_kernel(
    const float* __restrict__ X, const float* __restrict__ Wv, const float* __restrict__ bv)
{
    extern __shared__ char smem[];
    const int tid = threadIdx.x, wid = tid >> 5, lane = tid & 31;
    const int g = lane >> 2, tg = lane & 3;
    const int m0 = blockIdx.y * 128, n0 = blockIdx.x * 128;

    float acc[2][8][4] = {};
    gemm_main(Wv + (size_t)m0 * DIM, DIM, X + (size_t)n0 * DIM, DIM, DIM, acc, smem, tid);

    const int wm = (wid & 3) * 32, wn = (wid >> 2) * 64;
    const int b = n0 >> 11;           // token block fits in one batch (128 | 2048)
    #pragma unroll
    for (int mt = 0; mt < 2; mt++) {
        int e = m0 + wm + mt * 16 + g;
        float be0 = bv[e], be1 = bv[e + 8];
        #pragma unroll
        for (int nt = 0; nt < 8; nt++) {
            int t = n0 + wn + nt * 8 + tg * 2;
            int s = t & 2047;
            float2 v0 = make_float2(acc[mt][nt][0] + be0, acc[mt][nt][1] + be0);
            float2 v1 = make_float2(acc[mt][nt][2] + be1, acc[mt][nt][3] + be1);
            *(float2*)&g_Vt[((size_t)b * DIM + e) * SEQ + s] = v0;
            *(float2*)&g_Vt[((size_t)b * DIM + e + 8) * SEQ + s] = v1;
        }
    }
}

// scores: C[q][k] = Q[q]·K[k]; weights[b][q][k] = masked(scale*c)
__global__ __launch_bounds__(256, 1) void scores_kernel(
    const int* __restrict__ mask, float* __restrict__ out_w, float scale)
{
    extern __shared__ char smem[];
    const int tid = threadIdx.x, wid = tid >> 5, lane = tid & 31;
    const int g = lane >> 2, tg = lane & 3;
    const int b = blockIdx.z;
    const int m0 = blockIdx.y * 128, n0 = blockIdx.x * 128;
    const float* Qb = g_Q + (size_t)b * SEQ * DIM;
    const float* Kb = g_K + (size_t)b * SEQ * DIM;

    float acc[2][8][4] = {};
    gemm_main(Qb + (size_t)m0 * DIM, DIM, Kb + (size_t)n0 * DIM, DIM, DIM, acc, smem, tid);

    const int wm = (wid & 3) * 32, wn = (wid >> 2) * 64;
    const size_t base = (size_t)b * SEQ * SEQ;
    #pragma unroll
    for (int mt = 0; mt < 2; mt++) {
        int q = m0 + wm + mt * 16 + g;
        #pragma unroll
        for (int nt = 0; nt < 8; nt++) {
            int n = n0 + wn + nt * 8 + tg * 2;
            size_t i0 = base + (size_t)q * SEQ + n;
            size_t i1 = base + (size_t)(q + 8) * SEQ + n;
            int2 mk0 = *(const int2*)&mask[i0];
            int2 mk1 = *(const int2*)&mask[i1];
            float2 v0 = make_float2(mk0.x ? acc[mt][nt][0] * scale : -1e9f,
                                    mk0.y ? acc[mt][nt][1] * scale : -1e9f);
            float2 v1 = make_float2(mk1.x ? acc[mt][nt][2] * scale : -1e9f,
                                    mk1.y ? acc[mt][nt][3] * scale : -1e9f);
            *(float2*)&out_w[i0] = v0;
            *(float2*)&out_w[i1] = v1;
        }
    }
}

// out: C[q][d] = Wgt[q]·Vt[d]; Sout[b][q][d]
__global__ __launch_bounds__(256, 1) void out_kernel(
    const float* __restrict__ Wgt, float* __restrict__ O)
{
    extern __shared__ char smem[];
    const int tid = threadIdx.x, wid = tid >> 5, lane = tid & 31;
    const int g = lane >> 2, tg = lane & 3;
    const int b = blockIdx.z;
    const int m0 = blockIdx.y * 128, n0 = blockIdx.x * 128;
    const float* Ab = Wgt + (size_t)b * SEQ * SEQ;
    const float* Bb = g_Vt + (size_t)b * DIM * SEQ;

    float acc[2][8][4] = {};
    gemm_main(Ab + (size_t)m0 * SEQ, SEQ, Bb + (size_t)n0 * SEQ, SEQ, SEQ, acc, smem, tid);

    const int wm = (wid & 3) * 32, wn = (wid >> 2) * 64;
    float* Ob = O + (size_t)b * SEQ * DIM;
    #pragma unroll
    for (int mt = 0; mt < 2; mt++) {
        int q = m0 + wm + mt * 16 + g;
        #pragma unroll
        for (int nt = 0; nt < 8; nt++) {
            int n = n0 + wn + nt * 8 + tg * 2;
            *(float2*)&Ob[(size_t)q * DIM + n] = make_float2(acc[mt][nt][0], acc[mt][nt][1]);
            *(float2*)&Ob[(size_t)(q + 8) * DIM + n] = make_float2(acc[mt][nt][2], acc[mt][nt][3]);
        }
    }
}

// -------- softmax over rows of 2048, in place --------
__global__ __launch_bounds__(256) void softmax_kernel(float* __restrict__ W)
{
    float4* p = (float4*)(W + (size_t)blockIdx.x * SEQ);
    const int tid = threadIdx.x;

    float4 v[2];
    float m = -INFINITY;
    #pragma unroll
    for (int i = 0; i < 2; i++) {
        v[i] = p[tid + i * 256];
        m = fmaxf(m, fmaxf(fmaxf(v[i].x, v[i].y), fmaxf(v[i].z, v[i].w)));
    }
    __shared__ float red[256];
    red[tid] = m; __syncthreads();
    #pragma unroll
    for (int s = 128; s > 0; s >>= 1) { if (tid < s) red[tid] = fmaxf(red[tid], red[tid + s]); __syncthreads(); }
    m = red[0]; __syncthreads();

    float sum = 0.0f;
    #pragma unroll
    for (int i = 0; i < 2; i++) {
        v[i].x = __expf(v[i].x - m); v[i].y = __expf(v[i].y - m);
        v[i].z = __expf(v[i].z - m); v[i].w = __expf(v[i].w - m);
        sum += v[i].x + v[i].y + v[i].z + v[i].w;
    }
    red[tid] = sum; __syncthreads();
    #pragma unroll
    for (int s = 128; s > 0; s >>= 1) { if (tid < s) red[tid] += red[tid + s]; __syncthreads(); }
    float inv = 1.0f / red[0];

    #pragma unroll
    for (int i = 0; i < 2; i++) {
        v[i].x *= inv; v[i].y *= inv; v[i].z *= inv; v[i].w *= inv;
        p[tid + i * 256] = v[i];
    }
}

// ================= launch =================
extern "C" void kernel_launch(void* const* d_in, const int* in_sizes, int n_in,
                              void* d_out, int out_size)
{
    const float* X  = (const float*)d_in[0];
    const int*   mk = (const int*)  d_in[1];
    const float* Wq = (const float*)d_in[2];
    const float* bq = (const float*)d_in[3];
    const float* Wk = (const float*)d_in[4];
    const float* bk = (const float*)d_in[5];
    const float* Wv = (const float*)d_in[6];
    const float* bv = (const float*)d_in[7];

    float* out   = (float*)d_out;
    float* out_S = out;                              // [B, S, D]
    float* out_W = out + (size_t)BATCH * SEQ * DIM;  // [B, S, S]
    const float scale = 1.0f / sqrtf((float)DIM);

    static bool attr_set = false;
    if (!attr_set) {
        cudaFuncSetAttribute(qk_proj_kernel, cudaFuncAttributeMaxDynamicSharedMemorySize, SMEM_BYTES);
        cudaFuncSetAttribute(v_proj_kernel,  cudaFuncAttributeMaxDynamicSharedMemorySize, SMEM_BYTES);
        cudaFuncSetAttribute(scores_kernel,  cudaFuncAttributeMaxDynamicSharedMemorySize, SMEM_BYTES);
        cudaFuncSetAttribute(out_kernel,     cudaFuncAttributeMaxDynamicSharedMemorySize, SMEM_BYTES);
        attr_set = true;
    }

    qk_proj_kernel<<<dim3(4, 128, 2), 256, SMEM_BYTES>>>(X, Wq, bq, Wk, bk);
    v_proj_kernel<<<dim3(128, 4, 1), 256, SMEM_BYTES>>>(X, Wv, bv);
    scores_kernel<<<dim3(16, 16, 8), 256, SMEM_BYTES>>>(mk, out_W, scale);
    softmax_kernel<<<BATCH * SEQ, 256>>>(out_W);
    out_kernel<<<dim3(4, 16, 8), 256, SMEM_BYTES>>>(out_W, out_S);
}

// round 4
// speedup vs baseline: 2.2479x; 1.5818x over previous
#include <cuda_runtime.h>
#include <cuda_fp16.h>
#include <cstdint>
#include <cmath>

#define BATCH 8
#define SEQ   2048
#define DIM   512
#define MROWS (BATCH * SEQ)   // 16384

// -------- fp16 hi/lo scratch (allocation-free) --------
__device__ __half g_Xh[MROWS * DIM],  g_Xl[MROWS * DIM];
__device__ __half g_Wqh[DIM * DIM],   g_Wql[DIM * DIM];
__device__ __half g_Wkh[DIM * DIM],   g_Wkl[DIM * DIM];
__device__ __half g_Wvh[DIM * DIM],   g_Wvl[DIM * DIM];
__device__ __half g_Qh[MROWS * DIM],  g_Ql[MROWS * DIM];
__device__ __half g_Kh[MROWS * DIM],  g_Kl[MROWS * DIM];
__device__ __half g_Vth[BATCH * DIM * SEQ], g_Vtl[BATCH * DIM * SEQ];
__device__ __half g_Wth[(size_t)BATCH * SEQ * SEQ], g_Wtl[(size_t)BATCH * SEQ * SEQ];

// -------- tiling --------
#define BK 32
#define STAGES 4
#define TILE_B  8192                        // 128 rows x 32 f16
#define STAGE_B (4 * TILE_B)                // Ah, Al, Bh, Bl
#define SMEM_BYTES (STAGES * STAGE_B)       // 128 KB
#define OFF_AH 0
#define OFF_AL 8192
#define OFF_BH 16384
#define OFF_BL 24576

// ================= PTX helpers =================
__device__ __forceinline__ uint32_t smem_u32(const void* p) {
    uint32_t a;
    asm("{ .reg .u64 t; cvta.to.shared.u64 t, %1; cvt.u32.u64 %0, t; }" : "=r"(a) : "l"(p));
    return a;
}
__device__ __forceinline__ void cp16(uint32_t dst, const void* src) {
    asm volatile("cp.async.cg.shared.global [%0], [%1], 16;" :: "r"(dst), "l"(src));
}
#define CP_COMMIT() asm volatile("cp.async.commit_group;" ::: "memory")
#define CP_WAIT2()  asm volatile("cp.async.wait_group 2;" ::: "memory")

__device__ __forceinline__ void ldm4(uint32_t* d, uint32_t addr) {
    asm volatile("ldmatrix.sync.aligned.m8n8.x4.shared.b16 {%0,%1,%2,%3}, [%4];"
        : "=r"(d[0]), "=r"(d[1]), "=r"(d[2]), "=r"(d[3]) : "r"(addr));
}
__device__ __forceinline__ void mma16(float* d, const uint32_t* a, uint32_t b0, uint32_t b1) {
    asm volatile("mma.sync.aligned.m16n8k16.row.col.f32.f16.f16.f32 "
        "{%0,%1,%2,%3}, {%4,%5,%6,%7}, {%8,%9}, {%0,%1,%2,%3};"
        : "+f"(d[0]), "+f"(d[1]), "+f"(d[2]), "+f"(d[3])
        : "r"(a[0]), "r"(a[1]), "r"(a[2]), "r"(a[3]), "r"(b0), "r"(b1));
}

// Packed tile layout: 128 rows x 32 f16. Line L (128B) holds rows 2L, 2L+1.
// 16B chunk c (0..3) of row r lives at: (r>>1)*128 + (r&1)*64 + (((c + (r>>1)) & 3)<<4)
// -> conflict-free for ldmatrix (8 consecutive rows, fixed c, hit 8 distinct 16B groups).
__device__ __forceinline__ uint32_t tile_addr(uint32_t base, int r, int c) {
    return base + (uint32_t)(((r >> 1) * 128) + ((r & 1) * 64) + ((((c + (r >> 1)) & 3)) << 4));
}

// Producer: 128x32 f16 tile, 512 chunks, 2 per thread.
__device__ __forceinline__ void load_tile(uint32_t sdst, const __half* __restrict__ src,
                                          int ld, int kt, int tid)
{
    #pragma unroll
    for (int i = 0; i < 2; i++) {
        int ch = tid + i * 256;
        int r = ch >> 2, c = ch & 3;
        cp16(tile_addr(sdst, r, c), src + (size_t)r * ld + kt + c * 8);
    }
}

// ================= GEMM mainloop =================
// acc = A(128 x ktot) * B(128 x ktot)^T, A = Ah+Al, B = Bh+Bl (drop lo*lo).
__device__ __forceinline__ void gemm_main(
    const __half* __restrict__ Ah, const __half* __restrict__ Al, int lda,
    const __half* __restrict__ Bh, const __half* __restrict__ Bl, int ldb,
    int ktot, float (&acc)[2][8][4], char* smem, int tid)
{
    const int wid = tid >> 5, lane = tid & 31;
    const int wm = (wid & 3) * 32, wn = (wid >> 2) * 64;
    const int q = lane >> 3;
    const int lrow = (lane & 7) + (q & 1) * 8;   // row offset within 16-row block
    const int qc = q >> 1;                        // chunk offset (0/1)
    const uint32_t sbase = smem_u32(smem);
    const int NK = ktot / BK;

    int pf = 0;
    #pragma unroll
    for (int s = 0; s < STAGES - 1; s++) {
        if (pf < NK) {
            uint32_t sp = sbase + (uint32_t)(pf & (STAGES - 1)) * STAGE_B;
            load_tile(sp + OFF_AH, Ah, lda, pf * BK, tid);
            load_tile(sp + OFF_AL, Al, lda, pf * BK, tid);
            load_tile(sp + OFF_BH, Bh, ldb, pf * BK, tid);
            load_tile(sp + OFF_BL, Bl, ldb, pf * BK, tid);
            CP_COMMIT();
            pf++;
        }
    }

    for (int kb = 0; kb < NK; kb++) {
        CP_WAIT2();
        __syncthreads();
        const uint32_t st = sbase + (uint32_t)(kb & (STAGES - 1)) * STAGE_B;

        if (pf < NK) {
            uint32_t sp = sbase + (uint32_t)(pf & (STAGES - 1)) * STAGE_B;
            load_tile(sp + OFF_AH, Ah, lda, pf * BK, tid);
            load_tile(sp + OFF_AL, Al, lda, pf * BK, tid);
            load_tile(sp + OFF_BH, Bh, ldb, pf * BK, tid);
            load_tile(sp + OFF_BL, Bl, ldb, pf * BK, tid);
            CP_COMMIT();
            pf++;
        }

        #pragma unroll
        for (int ks = 0; ks < 2; ks++) {
            const int c = 2 * ks + qc;
            uint32_t ah[2][4], al[2][4];
            #pragma unroll
            for (int mt = 0; mt < 2; mt++) {
                ldm4(ah[mt], tile_addr(st + OFF_AH, wm + mt * 16 + lrow, c));
                ldm4(al[mt], tile_addr(st + OFF_AL, wm + mt * 16 + lrow, c));
            }
            uint32_t bh[4][4], bl[4][4];
            #pragma unroll
            for (int nb = 0; nb < 4; nb++) {
                ldm4(bh[nb], tile_addr(st + OFF_BH, wn + nb * 16 + lrow, c));
                ldm4(bl[nb], tile_addr(st + OFF_BL, wn + nb * 16 + lrow, c));
            }
            // pass hi*hi
            #pragma unroll
            for (int mt = 0; mt < 2; mt++)
                #pragma unroll
                for (int nb = 0; nb < 4; nb++) {
                    mma16(acc[mt][nb * 2 + 0], ah[mt], bh[nb][0], bh[nb][2]);
                    mma16(acc[mt][nb * 2 + 1], ah[mt], bh[nb][1], bh[nb][3]);
                }
            // pass hi*lo
            #pragma unroll
            for (int mt = 0; mt < 2; mt++)
                #pragma unroll
                for (int nb = 0; nb < 4; nb++) {
                    mma16(acc[mt][nb * 2 + 0], ah[mt], bl[nb][0], bl[nb][2]);
                    mma16(acc[mt][nb * 2 + 1], ah[mt], bl[nb][1], bl[nb][3]);
                }
            // pass lo*hi
            #pragma unroll
            for (int mt = 0; mt < 2; mt++)
                #pragma unroll
                for (int nb = 0; nb < 4; nb++) {
                    mma16(acc[mt][nb * 2 + 0], al[mt], bh[nb][0], bh[nb][2]);
                    mma16(acc[mt][nb * 2 + 1], al[mt], bh[nb][1], bh[nb][3]);
                }
        }
    }
}

__device__ __forceinline__ void split2(float x, float y, __half2& h, __half2& l) {
    __half hx = __float2half_rn(x), hy = __float2half_rn(y);
    h = __halves2half2(hx, hy);
    l = __halves2half2(__float2half_rn(x - __half2float(hx)),
                       __float2half_rn(y - __half2float(hy)));
}

// ================= kernels =================
// Convert fp32 array -> (hi, lo) fp16 arrays, 4 elems/thread.
__global__ __launch_bounds__(256) void cvt_split_kernel(
    const float* __restrict__ src, __half* __restrict__ h, __half* __restrict__ l, int n4)
{
    int i = blockIdx.x * 256 + threadIdx.x;
    if (i >= n4) return;
    float4 v = ((const float4*)src)[i];
    __half2 h0, l0, h1, l1;
    split2(v.x, v.y, h0, l0);
    split2(v.z, v.w, h1, l1);
    ((__half2*)h)[i * 2] = h0; ((__half2*)h)[i * 2 + 1] = h1;
    ((__half2*)l)[i * 2] = l0; ((__half2*)l)[i * 2 + 1] = l1;
}

// Q/K projection: C[t][e] = X[t]·W[e] + b[e]; writes fp16 hi/lo Q or K.
__global__ __launch_bounds__(256, 1) void qk_proj_kernel(
    const float* __restrict__ bq, const float* __restrict__ bk)
{
    extern __shared__ char smem[];
    const int tid = threadIdx.x, wid = tid >> 5, lane = tid & 31;
    const int g = lane >> 2, tg = lane & 3;
    const int m0 = blockIdx.y * 128, n0 = blockIdx.x * 128;
    const __half* Wh = blockIdx.z ? g_Wkh : g_Wqh;
    const __half* Wl = blockIdx.z ? g_Wkl : g_Wql;
    const float* bias = blockIdx.z ? bk : bq;
    __half* Oh = blockIdx.z ? g_Kh : g_Qh;
    __half* Ol = blockIdx.z ? g_Kl : g_Ql;

    float acc[2][8][4] = {};
    gemm_main(g_Xh + (size_t)m0 * DIM, g_Xl + (size_t)m0 * DIM, DIM,
              Wh + (size_t)n0 * DIM, Wl + (size_t)n0 * DIM, DIM,
              DIM, acc, smem, tid);

    const int wm = (wid & 3) * 32, wn = (wid >> 2) * 64;
    #pragma unroll
    for (int mt = 0; mt < 2; mt++) {
        int m = m0 + wm + mt * 16 + g;
        #pragma unroll
        for (int nt = 0; nt < 8; nt++) {
            int n = n0 + wn + nt * 8 + tg * 2;
            float b0 = bias[n], b1 = bias[n + 1];
            __half2 h, l;
            split2(acc[mt][nt][0] + b0, acc[mt][nt][1] + b1, h, l);
            *(__half2*)&Oh[(size_t)m * DIM + n] = h;
            *(__half2*)&Ol[(size_t)m * DIM + n] = l;
            split2(acc[mt][nt][2] + b0, acc[mt][nt][3] + b1, h, l);
            *(__half2*)&Oh[(size_t)(m + 8) * DIM + n] = h;
            *(__half2*)&Ol[(size_t)(m + 8) * DIM + n] = l;
        }
    }
}

// V projection transposed: C[e][t] = Wv[e]·X[t] + bv[e]; writes Vt hi/lo [b][e][s].
__global__ __launch_bounds__(256, 1) void v_proj_kernel(const float* __restrict__ bv)
{
    extern __shared__ char smem[];
    const int tid = threadIdx.x, wid = tid >> 5, lane = tid & 31;
    const int g = lane >> 2, tg = lane & 3;
    const int m0 = blockIdx.y * 128, n0 = blockIdx.x * 128;

    float acc[2][8][4] = {};
    gemm_main(g_Wvh + (size_t)m0 * DIM, g_Wvl + (size_t)m0 * DIM, DIM,
              g_Xh + (size_t)n0 * DIM, g_Xl + (size_t)n0 * DIM, DIM,
              DIM, acc, smem, tid);

    const int wm = (wid & 3) * 32, wn = (wid >> 2) * 64;
    const int b = n0 >> 11;
    #pragma unroll
    for (int mt = 0; mt < 2; mt++) {
        int e = m0 + wm + mt * 16 + g;
        float be0 = bv[e], be1 = bv[e + 8];
        #pragma unroll
        for (int nt = 0; nt < 8; nt++) {
            int t = n0 + wn + nt * 8 + tg * 2;
            int s = t & 2047;
            __half2 h, l;
            split2(acc[mt][nt][0] + be0, acc[mt][nt][1] + be0, h, l);
            *(__half2*)&g_Vth[((size_t)b * DIM + e) * SEQ + s] = h;
            *(__half2*)&g_Vtl[((size_t)b * DIM + e) * SEQ + s] = l;
            split2(acc[mt][nt][2] + be1, acc[mt][nt][3] + be1, h, l);
            *(__half2*)&g_Vth[((size_t)b * DIM + e + 8) * SEQ + s] = h;
            *(__half2*)&g_Vtl[((size_t)b * DIM + e + 8) * SEQ + s] = l;
        }
    }
}

// scores: C[q][k] = Q[q]·K[k]; weights[b][q][k] = masked(scale*c), fp32.
__global__ __launch_bounds__(256, 1) void scores_kernel(
    const int* __restrict__ mask, float* __restrict__ out_w, float scale)
{
    extern __shared__ char smem[];
    const int tid = threadIdx.x, wid = tid >> 5, lane = tid & 31;
    const int g = lane >> 2, tg = lane & 3;
    const int b = blockIdx.z;
    const int m0 = blockIdx.y * 128, n0 = blockIdx.x * 128;
    const size_t qoff = ((size_t)b * SEQ + m0) * DIM;
    const size_t koff = ((size_t)b * SEQ + n0) * DIM;

    float acc[2][8][4] = {};
    gemm_main(g_Qh + qoff, g_Ql + qoff, DIM, g_Kh + koff, g_Kl + koff, DIM,
              DIM, acc, smem, tid);

    const int wm = (wid & 3) * 32, wn = (wid >> 2) * 64;
    const size_t base = (size_t)b * SEQ * SEQ;
    #pragma unroll
    for (int mt = 0; mt < 2; mt++) {
        int qq = m0 + wm + mt * 16 + g;
        #pragma unroll
        for (int nt = 0; nt < 8; nt++) {
            int n = n0 + wn + nt * 8 + tg * 2;
            size_t i0 = base + (size_t)qq * SEQ + n;
            size_t i1 = base + (size_t)(qq + 8) * SEQ + n;
            int2 mk0 = *(const int2*)&mask[i0];
            int2 mk1 = *(const int2*)&mask[i1];
            *(float2*)&out_w[i0] = make_float2(mk0.x ? acc[mt][nt][0] * scale : -1e9f,
                                              mk0.y ? acc[mt][nt][1] * scale : -1e9f);
            *(float2*)&out_w[i1] = make_float2(mk1.x ? acc[mt][nt][2] * scale : -1e9f,
                                              mk1.y ? acc[mt][nt][3] * scale : -1e9f);
        }
    }
}

// softmax in place (fp32) + emit fp16 hi/lo copy for the out GEMM.
__global__ __launch_bounds__(256) void softmax_kernel(
    float* __restrict__ W, __half* __restrict__ Wh, __half* __restrict__ Wl)
{
    const size_t rowb = (size_t)blockIdx.x * SEQ;
    float4* p = (float4*)(W + rowb);
    __half2* ph = (__half2*)(Wh + rowb);
    __half2* pl = (__half2*)(Wl + rowb);
    const int tid = threadIdx.x;

    float4 v[2];
    float m = -INFINITY;
    #pragma unroll
    for (int i = 0; i < 2; i++) {
        v[i] = p[tid + i * 256];
        m = fmaxf(m, fmaxf(fmaxf(v[i].x, v[i].y), fmaxf(v[i].z, v[i].w)));
    }
    __shared__ float red[256];
    red[tid] = m; __syncthreads();
    #pragma unroll
    for (int s = 128; s > 0; s >>= 1) { if (tid < s) red[tid] = fmaxf(red[tid], red[tid + s]); __syncthreads(); }
    m = red[0]; __syncthreads();

    float sum = 0.0f;
    #pragma unroll
    for (int i = 0; i < 2; i++) {
        v[i].x = __expf(v[i].x - m); v[i].y = __expf(v[i].y - m);
        v[i].z = __expf(v[i].z - m); v[i].w = __expf(v[i].w - m);
        sum += v[i].x + v[i].y + v[i].z + v[i].w;
    }
    red[tid] = sum; __syncthreads();
    #pragma unroll
    for (int s = 128; s > 0; s >>= 1) { if (tid < s) red[tid] += red[tid + s]; __syncthreads(); }
    float inv = 1.0f / red[0];

    #pragma unroll
    for (int i = 0; i < 2; i++) {
        int j = tid + i * 256;
        v[i].x *= inv; v[i].y *= inv; v[i].z *= inv; v[i].w *= inv;
        p[j] = v[i];
        __half2 h0, l0, h1, l1;
        split2(v[i].x, v[i].y, h0, l0);
        split2(v[i].z, v[i].w, h1, l1);
        ph[j * 2] = h0; ph[j * 2 + 1] = h1;
        pl[j * 2] = l0; pl[j * 2 + 1] = l1;
    }
}

// out: C[q][d] = Wgt[q]·Vt[d]; Sout[b][q][d] fp32.
__global__ __launch_bounds__(256, 1) void out_kernel(float* __restrict__ O)
{
    extern __shared__ char smem[];
    const int tid = threadIdx.x, wid = tid >> 5, lane = tid & 31;
    const int g = lane >> 2, tg = lane & 3;
    const int b = blockIdx.z;
    const int m0 = blockIdx.y * 128, n0 = blockIdx.x * 128;
    const size_t aoff = (size_t)b * SEQ * SEQ + (size_t)m0 * SEQ;
    const size_t boff = (size_t)b * DIM * SEQ + (size_t)n0 * SEQ;

    float acc[2][8][4] = {};
    gemm_main(g_Wth + aoff, g_Wtl + aoff, SEQ, g_Vth + boff, g_Vtl + boff, SEQ,
              SEQ, acc, smem, tid);

    const int wm = (wid & 3) * 32, wn = (wid >> 2) * 64;
    float* Ob = O + (size_t)b * SEQ * DIM;
    #pragma unroll
    for (int mt = 0; mt < 2; mt++) {
        int qq = m0 + wm + mt * 16 + g;
        #pragma unroll
        for (int nt = 0; nt < 8; nt++) {
            int n = n0 + wn + nt * 8 + tg * 2;
            *(float2*)&Ob[(size_t)qq * DIM + n] = make_float2(acc[mt][nt][0], acc[mt][nt][1]);
            *(float2*)&Ob[(size_t)(qq + 8) * DIM + n] = make_float2(acc[mt][nt][2], acc[mt][nt][3]);
        }
    }
}

// ================= launch =================
extern "C" void kernel_launch(void* const* d_in, const int* in_sizes, int n_in,
                              void* d_out, int out_size)
{
    const float* X  = (const float*)d_in[0];
    const int*   mk = (const int*)  d_in[1];
    const float* Wq = (const float*)d_in[2];
    const float* bq = (const float*)d_in[3];
    const float* Wk = (const float*)d_in[4];
    const float* bk = (const float*)d_in[5];
    const float* Wv = (const float*)d_in[6];
    const float* bv = (const float*)d_in[7];

    float* out   = (float*)d_out;
    float* out_S = out;                              // [B, S, D]
    float* out_W = out + (size_t)BATCH * SEQ * DIM;  // [B, S, S]
    const float scale = 1.0f / sqrtf((float)DIM);

    cudaFuncSetAttribute(qk_proj_kernel, cudaFuncAttributeMaxDynamicSharedMemorySize, SMEM_BYTES);
    cudaFuncSetAttribute(v_proj_kernel,  cudaFuncAttributeMaxDynamicSharedMemorySize, SMEM_BYTES);
    cudaFuncSetAttribute(scores_kernel,  cudaFuncAttributeMaxDynamicSharedMemorySize, SMEM_BYTES);
    cudaFuncSetAttribute(out_kernel,     cudaFuncAttributeMaxDynamicSharedMemorySize, SMEM_BYTES);

    __half *xh, *xl, *wqh, *wql, *wkh, *wkl, *wvh, *wvl;
    cudaGetSymbolAddress((void**)&xh,  g_Xh);  cudaGetSymbolAddress((void**)&xl,  g_Xl);
    cudaGetSymbolAddress((void**)&wqh, g_Wqh); cudaGetSymbolAddress((void**)&wql, g_Wql);
    cudaGetSymbolAddress((void**)&wkh, g_Wkh); cudaGetSymbolAddress((void**)&wkl, g_Wkl);
    cudaGetSymbolAddress((void**)&wvh, g_Wvh); cudaGetSymbolAddress((void**)&wvl, g_Wvl);

    cvt_split_kernel<<<(MROWS * DIM / 4 + 255) / 256, 256>>>(X, xh, xl, MROWS * DIM / 4);
    cvt_split_kernel<<<(DIM * DIM / 4 + 255) / 256, 256>>>(Wq, wqh, wql, DIM * DIM / 4);
    cvt_split_kernel<<<(DIM * DIM / 4 + 255) / 256, 256>>>(Wk, wkh, wkl, DIM * DIM / 4);
    cvt_split_kernel<<<(DIM * DIM / 4 + 255) / 256, 256>>>(Wv, wvh, wvl, DIM * DIM / 4);

    qk_proj_kernel<<<dim3(4, 128, 2), 256, SMEM_BYTES>>>(bq, bk);
    v_proj_kernel<<<dim3(128, 4, 1), 256, SMEM_BYTES>>>(bv);
    scores_kernel<<<dim3(16, 16, 8), 256, SMEM_BYTES>>>(mk, out_W, scale);

    __half *wth, *wtl;
    cudaGetSymbolAddress((void**)&wth, g_Wth);
    cudaGetSymbolAddress((void**)&wtl, g_Wtl);
    softmax_kernel<<<BATCH * SEQ, 256>>>(out_W, wth, wtl);
    out_kernel<<<dim3(4, 16, 8), 256, SMEM_BYTES>>>(out_S);
}

// round 5
// speedup vs baseline: 2.9135x; 1.2961x over previous
#include <cuda_runtime.h>
#include <cuda_fp16.h>
#include <cstdint>
#include <cmath>

#define BATCH 8
#define SEQ   2048
#define DIM   512
#define MROWS (BATCH * SEQ)   // 16384

// -------- fp16 hi/lo scratch (allocation-free) --------
__device__ __half g_Xh[MROWS * DIM],  g_Xl[MROWS * DIM];
__device__ __half g_Wqh[DIM * DIM],   g_Wql[DIM * DIM];
__device__ __half g_Wkh[DIM * DIM],   g_Wkl[DIM * DIM];
__device__ __half g_Wvh[DIM * DIM],   g_Wvl[DIM * DIM];
__device__ __half g_Qh[MROWS * DIM],  g_Ql[MROWS * DIM];
__device__ __half g_Kh[MROWS * DIM],  g_Kl[MROWS * DIM];
__device__ __half g_Vth[BATCH * DIM * SEQ];
__device__ __half g_Wth[(size_t)BATCH * SEQ * SEQ];

// -------- tiling --------
#define BK 32
#define STAGES 4
#define TILE_B  8192                        // 128 rows x 32 f16
// 3-pass layout: Ah, Al, Bh, Bl per stage
#define STAGE_B (4 * TILE_B)
#define SMEM_BYTES (STAGES * STAGE_B)       // 128 KB
#define OFF_AH 0
#define OFF_AL 8192
#define OFF_BH 16384
#define OFF_BL 24576
// 1-pass layout: Ah, Bh per stage
#define STAGE1_B (2 * TILE_B)
#define SMEM1_BYTES (STAGES * STAGE1_B)     // 64 KB
#define OFF1_BH 8192

// ================= PTX helpers =================
__device__ __forceinline__ uint32_t smem_u32(const void* p) {
    uint32_t a;
    asm("{ .reg .u64 t; cvta.to.shared.u64 t, %1; cvt.u32.u64 %0, t; }" : "=r"(a) : "l"(p));
    return a;
}
__device__ __forceinline__ void cp16(uint32_t dst, const void* src) {
    asm volatile("cp.async.cg.shared.global [%0], [%1], 16;" :: "r"(dst), "l"(src));
}
#define CP_COMMIT() asm volatile("cp.async.commit_group;" ::: "memory")
#define CP_WAIT2()  asm volatile("cp.async.wait_group 2;" ::: "memory")

__device__ __forceinline__ void ldm4(uint32_t* d, uint32_t addr) {
    asm volatile("ldmatrix.sync.aligned.m8n8.x4.shared.b16 {%0,%1,%2,%3}, [%4];"
        : "=r"(d[0]), "=r"(d[1]), "=r"(d[2]), "=r"(d[3]) : "r"(addr));
}
__device__ __forceinline__ void mma16(float* d, const uint32_t* a, uint32_t b0, uint32_t b1) {
    asm volatile("mma.sync.aligned.m16n8k16.row.col.f32.f16.f16.f32 "
        "{%0,%1,%2,%3}, {%4,%5,%6,%7}, {%8,%9}, {%0,%1,%2,%3};"
        : "+f"(d[0]), "+f"(d[1]), "+f"(d[2]), "+f"(d[3])
        : "r"(a[0]), "r"(a[1]), "r"(a[2]), "r"(a[3]), "r"(b0), "r"(b1));
}

// Packed tile layout: 128 rows x 32 f16; line L holds rows 2L, 2L+1; rotated 16B chunks.
__device__ __forceinline__ uint32_t tile_addr(uint32_t base, int r, int c) {
    return base + (uint32_t)(((r >> 1) * 128) + ((r & 1) * 64) + ((((c + (r >> 1)) & 3)) << 4));
}

// Producer: 128x32 f16 tile, 512 chunks, 2 per thread.
__device__ __forceinline__ void load_tile(uint32_t sdst, const __half* __restrict__ src,
                                          int ld, int kt, int tid)
{
    #pragma unroll
    for (int i = 0; i < 2; i++) {
        int ch = tid + i * 256;
        int r = ch >> 2, c = ch & 3;
        cp16(tile_addr(sdst, r, c), src + (size_t)r * ld + kt + c * 8);
    }
}

// ================= 3-pass GEMM mainloop =================
__device__ __forceinline__ void gemm_main(
    const __half* __restrict__ Ah, const __half* __restrict__ Al, int lda,
    const __half* __restrict__ Bh, const __half* __restrict__ Bl, int ldb,
    int ktot, float (&acc)[2][8][4], char* smem, int tid)
{
    const int wid = tid >> 5, lane = tid & 31;
    const int wm = (wid & 3) * 32, wn = (wid >> 2) * 64;
    const int q = lane >> 3;
    const int lrow = (lane & 7) + (q & 1) * 8;
    const int qc = q >> 1;
    const uint32_t sbase = smem_u32(smem);
    const int NK = ktot / BK;

    int pf = 0;
    #pragma unroll
    for (int s = 0; s < STAGES - 1; s++) {
        if (pf < NK) {
            uint32_t sp = sbase + (uint32_t)(pf & (STAGES - 1)) * STAGE_B;
            load_tile(sp + OFF_AH, Ah, lda, pf * BK, tid);
            load_tile(sp + OFF_AL, Al, lda, pf * BK, tid);
            load_tile(sp + OFF_BH, Bh, ldb, pf * BK, tid);
            load_tile(sp + OFF_BL, Bl, ldb, pf * BK, tid);
            CP_COMMIT();
            pf++;
        }
    }

    for (int kb = 0; kb < NK; kb++) {
        CP_WAIT2();
        __syncthreads();
        const uint32_t st = sbase + (uint32_t)(kb & (STAGES - 1)) * STAGE_B;

        if (pf < NK) {
            uint32_t sp = sbase + (uint32_t)(pf & (STAGES - 1)) * STAGE_B;
            load_tile(sp + OFF_AH, Ah, lda, pf * BK, tid);
            load_tile(sp + OFF_AL, Al, lda, pf * BK, tid);
            load_tile(sp + OFF_BH, Bh, ldb, pf * BK, tid);
            load_tile(sp + OFF_BL, Bl, ldb, pf * BK, tid);
            CP_COMMIT();
            pf++;
        }

        #pragma unroll
        for (int ks = 0; ks < 2; ks++) {
            const int c = 2 * ks + qc;
            uint32_t ah[2][4], al[2][4];
            #pragma unroll
            for (int mt = 0; mt < 2; mt++) {
                ldm4(ah[mt], tile_addr(st + OFF_AH, wm + mt * 16 + lrow, c));
                ldm4(al[mt], tile_addr(st + OFF_AL, wm + mt * 16 + lrow, c));
            }
            uint32_t bh[4][4], bl[4][4];
            #pragma unroll
            for (int nb = 0; nb < 4; nb++) {
                ldm4(bh[nb], tile_addr(st + OFF_BH, wn + nb * 16 + lrow, c));
                ldm4(bl[nb], tile_addr(st + OFF_BL, wn + nb * 16 + lrow, c));
            }
            #pragma unroll
            for (int mt = 0; mt < 2; mt++)
                #pragma unroll
                for (int nb = 0; nb < 4; nb++) {
                    mma16(acc[mt][nb * 2 + 0], ah[mt], bh[nb][0], bh[nb][2]);
                    mma16(acc[mt][nb * 2 + 1], ah[mt], bh[nb][1], bh[nb][3]);
                }
            #pragma unroll
            for (int mt = 0; mt < 2; mt++)
                #pragma unroll
                for (int nb = 0; nb < 4; nb++) {
                    mma16(acc[mt][nb * 2 + 0], ah[mt], bl[nb][0], bl[nb][2]);
                    mma16(acc[mt][nb * 2 + 1], ah[mt], bl[nb][1], bl[nb][3]);
                }
            #pragma unroll
            for (int mt = 0; mt < 2; mt++)
                #pragma unroll
                for (int nb = 0; nb < 4; nb++) {
                    mma16(acc[mt][nb * 2 + 0], al[mt], bh[nb][0], bh[nb][2]);
                    mma16(acc[mt][nb * 2 + 1], al[mt], bh[nb][1], bh[nb][3]);
                }
        }
    }
}

// ================= 1-pass GEMM mainloop (hi only) =================
__device__ __forceinline__ void gemm1_main(
    const __half* __restrict__ Ah, int lda,
    const __half* __restrict__ Bh, int ldb,
    int ktot, float (&acc)[2][8][4], char* smem, int tid)
{
    const int wid = tid >> 5, lane = tid & 31;
    const int wm = (wid & 3) * 32, wn = (wid >> 2) * 64;
    const int q = lane >> 3;
    const int lrow = (lane & 7) + (q & 1) * 8;
    const int qc = q >> 1;
    const uint32_t sbase = smem_u32(smem);
    const int NK = ktot / BK;

    int pf = 0;
    #pragma unroll
    for (int s = 0; s < STAGES - 1; s++) {
        if (pf < NK) {
            uint32_t sp = sbase + (uint32_t)(pf & (STAGES - 1)) * STAGE1_B;
            load_tile(sp, Ah, lda, pf * BK, tid);
            load_tile(sp + OFF1_BH, Bh, ldb, pf * BK, tid);
            CP_COMMIT();
            pf++;
        }
    }

    for (int kb = 0; kb < NK; kb++) {
        CP_WAIT2();
        __syncthreads();
        const uint32_t st = sbase + (uint32_t)(kb & (STAGES - 1)) * STAGE1_B;

        if (pf < NK) {
            uint32_t sp = sbase + (uint32_t)(pf & (STAGES - 1)) * STAGE1_B;
            load_tile(sp, Ah, lda, pf * BK, tid);
            load_tile(sp + OFF1_BH, Bh, ldb, pf * BK, tid);
            CP_COMMIT();
            pf++;
        }

        #pragma unroll
        for (int ks = 0; ks < 2; ks++) {
            const int c = 2 * ks + qc;
            uint32_t ah[2][4];
            #pragma unroll
            for (int mt = 0; mt < 2; mt++)
                ldm4(ah[mt], tile_addr(st, wm + mt * 16 + lrow, c));
            uint32_t bh[4][4];
            #pragma unroll
            for (int nb = 0; nb < 4; nb++)
                ldm4(bh[nb], tile_addr(st + OFF1_BH, wn + nb * 16 + lrow, c));
            #pragma unroll
            for (int mt = 0; mt < 2; mt++)
                #pragma unroll
                for (int nb = 0; nb < 4; nb++) {
                    mma16(acc[mt][nb * 2 + 0], ah[mt], bh[nb][0], bh[nb][2]);
                    mma16(acc[mt][nb * 2 + 1], ah[mt], bh[nb][1], bh[nb][3]);
                }
        }
    }
}

__device__ __forceinline__ void split2(float x, float y, __half2& h, __half2& l) {
    __half hx = __float2half_rn(x), hy = __float2half_rn(y);
    h = __halves2half2(hx, hy);
    l = __halves2half2(__float2half_rn(x - __half2float(hx)),
                       __float2half_rn(y - __half2float(hy)));
}

// ================= kernels =================
__global__ __launch_bounds__(256) void cvt_split_kernel(
    const float* __restrict__ src, __half* __restrict__ h, __half* __restrict__ l, int n4)
{
    int i = blockIdx.x * 256 + threadIdx.x;
    if (i >= n4) return;
    float4 v = ((const float4*)src)[i];
    __half2 h0, l0, h1, l1;
    split2(v.x, v.y, h0, l0);
    split2(v.z, v.w, h1, l1);
    ((__half2*)h)[i * 2] = h0; ((__half2*)h)[i * 2 + 1] = h1;
    ((__half2*)l)[i * 2] = l0; ((__half2*)l)[i * 2 + 1] = l1;
}

// Q/K projection
__global__ __launch_bounds__(256, 1) void qk_proj_kernel(
    const float* __restrict__ bq, const float* __restrict__ bk)
{
    extern __shared__ char smem[];
    const int tid = threadIdx.x, wid = tid >> 5, lane = tid & 31;
    const int g = lane >> 2, tg = lane & 3;
    const int m0 = blockIdx.y * 128, n0 = blockIdx.x * 128;
    const __half* Wh = blockIdx.z ? g_Wkh : g_Wqh;
    const __half* Wl = blockIdx.z ? g_Wkl : g_Wql;
    const float* bias = blockIdx.z ? bk : bq;
    __half* Oh = blockIdx.z ? g_Kh : g_Qh;
    __half* Ol = blockIdx.z ? g_Kl : g_Ql;

    float acc[2][8][4] = {};
    gemm_main(g_Xh + (size_t)m0 * DIM, g_Xl + (size_t)m0 * DIM, DIM,
              Wh + (size_t)n0 * DIM, Wl + (size_t)n0 * DIM, DIM,
              DIM, acc, smem, tid);

    const int wm = (wid & 3) * 32, wn = (wid >> 2) * 64;
    #pragma unroll
    for (int mt = 0; mt < 2; mt++) {
        int m = m0 + wm + mt * 16 + g;
        #pragma unroll
        for (int nt = 0; nt < 8; nt++) {
            int n = n0 + wn + nt * 8 + tg * 2;
            float b0 = bias[n], b1 = bias[n + 1];
            __half2 h, l;
            split2(acc[mt][nt][0] + b0, acc[mt][nt][1] + b1, h, l);
            *(__half2*)&Oh[(size_t)m * DIM + n] = h;
            *(__half2*)&Ol[(size_t)m * DIM + n] = l;
            split2(acc[mt][nt][2] + b0, acc[mt][nt][3] + b1, h, l);
            *(__half2*)&Oh[(size_t)(m + 8) * DIM + n] = h;
            *(__half2*)&Ol[(size_t)(m + 8) * DIM + n] = l;
        }
    }
}

// V projection transposed -> Vt hi only
__global__ __launch_bounds__(256, 1) void v_proj_kernel(const float* __restrict__ bv)
{
    extern __shared__ char smem[];
    const int tid = threadIdx.x, wid = tid >> 5, lane = tid & 31;
    const int g = lane >> 2, tg = lane & 3;
    const int m0 = blockIdx.y * 128, n0 = blockIdx.x * 128;

    float acc[2][8][4] = {};
    gemm_main(g_Wvh + (size_t)m0 * DIM, g_Wvl + (size_t)m0 * DIM, DIM,
              g_Xh + (size_t)n0 * DIM, g_Xl + (size_t)n0 * DIM, DIM,
              DIM, acc, smem, tid);

    const int wm = (wid & 3) * 32, wn = (wid >> 2) * 64;
    const int b = n0 >> 11;
    #pragma unroll
    for (int mt = 0; mt < 2; mt++) {
        int e = m0 + wm + mt * 16 + g;
        float be0 = bv[e], be1 = bv[e + 8];
        #pragma unroll
        for (int nt = 0; nt < 8; nt++) {
            int t = n0 + wn + nt * 8 + tg * 2;
            int s = t & 2047;
            __half2 h = __halves2half2(__float2half_rn(acc[mt][nt][0] + be0),
                                       __float2half_rn(acc[mt][nt][1] + be0));
            *(__half2*)&g_Vth[((size_t)b * DIM + e) * SEQ + s] = h;
            h = __halves2half2(__float2half_rn(acc[mt][nt][2] + be1),
                               __float2half_rn(acc[mt][nt][3] + be1));
            *(__half2*)&g_Vth[((size_t)b * DIM + e + 8) * SEQ + s] = h;
        }
    }
}

// scores (3-pass, masked, fp32 out)
__global__ __launch_bounds__(256, 1) void scores_kernel(
    const int* __restrict__ mask, float* __restrict__ out_w, float scale)
{
    extern __shared__ char smem[];
    const int tid = threadIdx.x, wid = tid >> 5, lane = tid & 31;
    const int g = lane >> 2, tg = lane & 3;
    const int b = blockIdx.z;
    const int m0 = blockIdx.y * 128, n0 = blockIdx.x * 128;
    const size_t qoff = ((size_t)b * SEQ + m0) * DIM;
    const size_t koff = ((size_t)b * SEQ + n0) * DIM;

    float acc[2][8][4] = {};
    gemm_main(g_Qh + qoff, g_Ql + qoff, DIM, g_Kh + koff, g_Kl + koff, DIM,
              DIM, acc, smem, tid);

    const int wm = (wid & 3) * 32, wn = (wid >> 2) * 64;
    const size_t base = (size_t)b * SEQ * SEQ;
    #pragma unroll
    for (int mt = 0; mt < 2; mt++) {
        int qq = m0 + wm + mt * 16 + g;
        #pragma unroll
        for (int nt = 0; nt < 8; nt++) {
            int n = n0 + wn + nt * 8 + tg * 2;
            size_t i0 = base + (size_t)qq * SEQ + n;
            size_t i1 = base + (size_t)(qq + 8) * SEQ + n;
            int2 mk0 = *(const int2*)&mask[i0];
            int2 mk1 = *(const int2*)&mask[i1];
            *(float2*)&out_w[i0] = make_float2(mk0.x ? acc[mt][nt][0] * scale : -1e9f,
                                              mk0.y ? acc[mt][nt][1] * scale : -1e9f);
            *(float2*)&out_w[i1] = make_float2(mk1.x ? acc[mt][nt][2] * scale : -1e9f,
                                              mk1.y ? acc[mt][nt][3] * scale : -1e9f);
        }
    }
}

// softmax in place (fp32) + fp16 hi copy only
__global__ __launch_bounds__(256) void softmax_kernel(
    float* __restrict__ W, __half* __restrict__ Wh)
{
    const size_t rowb = (size_t)blockIdx.x * SEQ;
    float4* p = (float4*)(W + rowb);
    __half2* ph = (__half2*)(Wh + rowb);
    const int tid = threadIdx.x;

    float4 v[2];
    float m = -INFINITY;
    #pragma unroll
    for (int i = 0; i < 2; i++) {
        v[i] = p[tid + i * 256];
        m = fmaxf(m, fmaxf(fmaxf(v[i].x, v[i].y), fmaxf(v[i].z, v[i].w)));
    }
    __shared__ float red[256];
    red[tid] = m; __syncthreads();
    #pragma unroll
    for (int s = 128; s > 0; s >>= 1) { if (tid < s) red[tid] = fmaxf(red[tid], red[tid + s]); __syncthreads(); }
    m = red[0]; __syncthreads();

    float sum = 0.0f;
    #pragma unroll
    for (int i = 0; i < 2; i++) {
        v[i].x = __expf(v[i].x - m); v[i].y = __expf(v[i].y - m);
        v[i].z = __expf(v[i].z - m); v[i].w = __expf(v[i].w - m);
        sum += v[i].x + v[i].y + v[i].z + v[i].w;
    }
    red[tid] = sum; __syncthreads();
    #pragma unroll
    for (int s = 128; s > 0; s >>= 1) { if (tid < s) red[tid] += red[tid + s]; __syncthreads(); }
    float inv = 1.0f / red[0];

    #pragma unroll
    for (int i = 0; i < 2; i++) {
        int j = tid + i * 256;
        v[i].x *= inv; v[i].y *= inv; v[i].z *= inv; v[i].w *= inv;
        p[j] = v[i];
        ph[j * 2]     = __halves2half2(__float2half_rn(v[i].x), __float2half_rn(v[i].y));
        ph[j * 2 + 1] = __halves2half2(__float2half_rn(v[i].z), __float2half_rn(v[i].w));
    }
}

// out (1-pass fp16): C[q][d] = Wgt_h[q]·Vt_h[d]
__global__ __launch_bounds__(256, 2) void out_kernel(float* __restrict__ O)
{
    extern __shared__ char smem[];
    const int tid = threadIdx.x, wid = tid >> 5, lane = tid & 31;
    const int g = lane >> 2, tg = lane & 3;
    const int b = blockIdx.z;
    const int m0 = blockIdx.y * 128, n0 = blockIdx.x * 128;
    const size_t aoff = (size_t)b * SEQ * SEQ + (size_t)m0 * SEQ;
    const size_t boff = (size_t)b * DIM * SEQ + (size_t)n0 * SEQ;

    float acc[2][8][4] = {};
    gemm1_main(g_Wth + aoff, SEQ, g_Vth + boff, SEQ, SEQ, acc, smem, tid);

    const int wm = (wid & 3) * 32, wn = (wid >> 2) * 64;
    float* Ob = O + (size_t)b * SEQ * DIM;
    #pragma unroll
    for (int mt = 0; mt < 2; mt++) {
        int qq = m0 + wm + mt * 16 + g;
        #pragma unroll
        for (int nt = 0; nt < 8; nt++) {
            int n = n0 + wn + nt * 8 + tg * 2;
            *(float2*)&Ob[(size_t)qq * DIM + n] = make_float2(acc[mt][nt][0], acc[mt][nt][1]);
            *(float2*)&Ob[(size_t)(qq + 8) * DIM + n] = make_float2(acc[mt][nt][2], acc[mt][nt][3]);
        }
    }
}

// ================= launch =================
extern "C" void kernel_launch(void* const* d_in, const int* in_sizes, int n_in,
                              void* d_out, int out_size)
{
    const float* X  = (const float*)d_in[0];
    const int*   mk = (const int*)  d_in[1];
    const float* Wq = (const float*)d_in[2];
    const float* bq = (const float*)d_in[3];
    const float* Wk = (const float*)d_in[4];
    const float* bk = (const float*)d_in[5];
    const float* Wv = (const float*)d_in[6];
    const float* bv = (const float*)d_in[7];

    float* out   = (float*)d_out;
    float* out_S = out;                              // [B, S, D]
    float* out_W = out + (size_t)BATCH * SEQ * DIM;  // [B, S, S]
    const float scale = 1.0f / sqrtf((float)DIM);

    cudaFuncSetAttribute(qk_proj_kernel, cudaFuncAttributeMaxDynamicSharedMemorySize, SMEM_BYTES);
    cudaFuncSetAttribute(v_proj_kernel,  cudaFuncAttributeMaxDynamicSharedMemorySize, SMEM_BYTES);
    cudaFuncSetAttribute(scores_kernel,  cudaFuncAttributeMaxDynamicSharedMemorySize, SMEM_BYTES);
    cudaFuncSetAttribute(out_kernel,     cudaFuncAttributeMaxDynamicSharedMemorySize, SMEM1_BYTES);

    __half *xh, *xl, *wqh, *wql, *wkh, *wkl, *wvh, *wvl, *wth;
    cudaGetSymbolAddress((void**)&xh,  g_Xh);  cudaGetSymbolAddress((void**)&xl,  g_Xl);
    cudaGetSymbolAddress((void**)&wqh, g_Wqh); cudaGetSymbolAddress((void**)&wql, g_Wql);
    cudaGetSymbolAddress((void**)&wkh, g_Wkh); cudaGetSymbolAddress((void**)&wkl, g_Wkl);
    cudaGetSymbolAddress((void**)&wvh, g_Wvh); cudaGetSymbolAddress((void**)&wvl, g_Wvl);
    cudaGetSymbolAddress((void**)&wth, g_Wth);

    cvt_split_kernel<<<(MROWS * DIM / 4 + 255) / 256, 256>>>(X, xh, xl, MROWS * DIM / 4);
    cvt_split_kernel<<<(DIM * DIM / 4 + 255) / 256, 256>>>(Wq, wqh, wql, DIM * DIM / 4);
    cvt_split_kernel<<<(DIM * DIM / 4 + 255) / 256, 256>>>(Wk, wkh, wkl, DIM * DIM / 4);
    cvt_split_kernel<<<(DIM * DIM / 4 + 255) / 256, 256>>>(Wv, wvh, wvl, DIM * DIM / 4);

    qk_proj_kernel<<<dim3(4, 128, 2), 256, SMEM_BYTES>>>(bq, bk);
    v_proj_kernel<<<dim3(128, 4, 1), 256, SMEM_BYTES>>>(bv);
    scores_kernel<<<dim3(16, 16, 8), 256, SMEM_BYTES>>>(mk, out_W, scale);
    softmax_kernel<<<BATCH * SEQ, 256>>>(out_W, wth);
    out_kernel<<<dim3(4, 16, 8), 256, SMEM1_BYTES>>>(out_S);
}

// round 6
// speedup vs baseline: 3.2566x; 1.1178x over previous
#include <cuda_runtime.h>
#include <cuda_fp16.h>
#include <cstdint>
#include <cmath>

#define BATCH 8
#define SEQ   2048
#define DIM   512
#define MROWS (BATCH * SEQ)   // 16384

// -------- fp16 hi/lo scratch (allocation-free) --------
__device__ __half g_Xh[MROWS * DIM],  g_Xl[MROWS * DIM];
__device__ __half g_Wqh[DIM * DIM],   g_Wql[DIM * DIM];
__device__ __half g_Wkh[DIM * DIM],   g_Wkl[DIM * DIM];
__device__ __half g_Wvh[DIM * DIM],   g_Wvl[DIM * DIM];
__device__ __half g_Qh[MROWS * DIM],  g_Ql[MROWS * DIM];
__device__ __half g_Kh[MROWS * DIM],  g_Kl[MROWS * DIM];
__device__ __half g_Vth[BATCH * DIM * SEQ];
__device__ __half g_Wth[(size_t)BATCH * SEQ * SEQ];

// -------- tiling --------
#define BK 32
#define TILE_B  8192                        // 128 rows x 32 f16
// 3-pass layout: Ah, Al, Bh, Bl per stage; 3 stages -> 96KB, occupancy 2
#define STAGES3 3
#define STAGE_B (4 * TILE_B)
#define SMEM3_BYTES (STAGES3 * STAGE_B)     // 98304
#define OFF_AH 0
#define OFF_AL 8192
#define OFF_BH 16384
#define OFF_BL 24576
// 1-pass layout: Ah, Bh per stage; 4 stages -> 64KB, occupancy 2
#define STAGES1 4
#define STAGE1_B (2 * TILE_B)
#define SMEM1_BYTES (STAGES1 * STAGE1_B)    // 65536
#define OFF1_BH 8192

// ================= PTX helpers =================
__device__ __forceinline__ uint32_t smem_u32(const void* p) {
    uint32_t a;
    asm("{ .reg .u64 t; cvta.to.shared.u64 t, %1; cvt.u32.u64 %0, t; }" : "=r"(a) : "l"(p));
    return a;
}
__device__ __forceinline__ void cp16(uint32_t dst, const void* src) {
    asm volatile("cp.async.cg.shared.global [%0], [%1], 16;" :: "r"(dst), "l"(src));
}
#define CP_COMMIT() asm volatile("cp.async.commit_group;" ::: "memory")
#define CP_WAIT1()  asm volatile("cp.async.wait_group 1;" ::: "memory")
#define CP_WAIT2()  asm volatile("cp.async.wait_group 2;" ::: "memory")

__device__ __forceinline__ void ldm4(uint32_t* d, uint32_t addr) {
    asm volatile("ldmatrix.sync.aligned.m8n8.x4.shared.b16 {%0,%1,%2,%3}, [%4];"
        : "=r"(d[0]), "=r"(d[1]), "=r"(d[2]), "=r"(d[3]) : "r"(addr));
}
__device__ __forceinline__ void mma16(float* d, const uint32_t* a, uint32_t b0, uint32_t b1) {
    asm volatile("mma.sync.aligned.m16n8k16.row.col.f32.f16.f16.f32 "
        "{%0,%1,%2,%3}, {%4,%5,%6,%7}, {%8,%9}, {%0,%1,%2,%3};"
        : "+f"(d[0]), "+f"(d[1]), "+f"(d[2]), "+f"(d[3])
        : "r"(a[0]), "r"(a[1]), "r"(a[2]), "r"(a[3]), "r"(b0), "r"(b1));
}

// Packed tile layout: 128 rows x 32 f16; line L holds rows 2L, 2L+1; rotated 16B chunks.
__device__ __forceinline__ uint32_t tile_addr(uint32_t base, int r, int c) {
    return base + (uint32_t)(((r >> 1) * 128) + ((r & 1) * 64) + ((((c + (r >> 1)) & 3)) << 4));
}

// Producer: 128x32 f16 tile, 512 chunks, 2 per thread.
__device__ __forceinline__ void load_tile(uint32_t sdst, const __half* __restrict__ src,
                                          int ld, int kt, int tid)
{
    #pragma unroll
    for (int i = 0; i < 2; i++) {
        int ch = tid + i * 256;
        int r = ch >> 2, c = ch & 3;
        cp16(tile_addr(sdst, r, c), src + (size_t)r * ld + kt + c * 8);
    }
}

// ================= 3-pass GEMM mainloop (3 smem stages) =================
__device__ __forceinline__ void gemm_main(
    const __half* __restrict__ Ah, const __half* __restrict__ Al, int lda,
    const __half* __restrict__ Bh, const __half* __restrict__ Bl, int ldb,
    int ktot, float (&acc)[2][8][4], char* smem, int tid)
{
    const int wid = tid >> 5, lane = tid & 31;
    const int wm = (wid & 3) * 32, wn = (wid >> 2) * 64;
    const int q = lane >> 3;
    const int lrow = (lane & 7) + (q & 1) * 8;
    const int qc = q >> 1;
    const uint32_t sbase = smem_u32(smem);
    const int NK = ktot / BK;

    int pf = 0, wrs = 0;
    #pragma unroll
    for (int s = 0; s < STAGES3 - 1; s++) {
        if (pf < NK) {
            uint32_t sp = sbase + (uint32_t)wrs * STAGE_B;
            load_tile(sp + OFF_AH, Ah, lda, pf * BK, tid);
            load_tile(sp + OFF_AL, Al, lda, pf * BK, tid);
            load_tile(sp + OFF_BH, Bh, ldb, pf * BK, tid);
            load_tile(sp + OFF_BL, Bl, ldb, pf * BK, tid);
            CP_COMMIT();
            pf++; wrs = (wrs == STAGES3 - 1) ? 0 : wrs + 1;
        }
    }

    int rds = 0;
    for (int kb = 0; kb < NK; kb++) {
        CP_WAIT1();
        __syncthreads();
        const uint32_t st = sbase + (uint32_t)rds * STAGE_B;
        rds = (rds == STAGES3 - 1) ? 0 : rds + 1;

        if (pf < NK) {
            uint32_t sp = sbase + (uint32_t)wrs * STAGE_B;
            load_tile(sp + OFF_AH, Ah, lda, pf * BK, tid);
            load_tile(sp + OFF_AL, Al, lda, pf * BK, tid);
            load_tile(sp + OFF_BH, Bh, ldb, pf * BK, tid);
            load_tile(sp + OFF_BL, Bl, ldb, pf * BK, tid);
            CP_COMMIT();
            pf++; wrs = (wrs == STAGES3 - 1) ? 0 : wrs + 1;
        } else {
            CP_COMMIT();   // keep group accounting uniform
        }

        #pragma unroll
        for (int ks = 0; ks < 2; ks++) {
            const int c = 2 * ks + qc;
            uint32_t ah[2][4], al[2][4];
            #pragma unroll
            for (int mt = 0; mt < 2; mt++) {
                ldm4(ah[mt], tile_addr(st + OFF_AH, wm + mt * 16 + lrow, c));
                ldm4(al[mt], tile_addr(st + OFF_AL, wm + mt * 16 + lrow, c));
            }
            uint32_t bh[4][4], bl[4][4];
            #pragma unroll
            for (int nb = 0; nb < 4; nb++) {
                ldm4(bh[nb], tile_addr(st + OFF_BH, wn + nb * 16 + lrow, c));
                ldm4(bl[nb], tile_addr(st + OFF_BL, wn + nb * 16 + lrow, c));
            }
            #pragma unroll
            for (int mt = 0; mt < 2; mt++)
                #pragma unroll
                for (int nb = 0; nb < 4; nb++) {
                    mma16(acc[mt][nb * 2 + 0], ah[mt], bh[nb][0], bh[nb][2]);
                    mma16(acc[mt][nb * 2 + 1], ah[mt], bh[nb][1], bh[nb][3]);
                }
            #pragma unroll
            for (int mt = 0; mt < 2; mt++)
                #pragma unroll
                for (int nb = 0; nb < 4; nb++) {
                    mma16(acc[mt][nb * 2 + 0], ah[mt], bl[nb][0], bl[nb][2]);
                    mma16(acc[mt][nb * 2 + 1], ah[mt], bl[nb][1], bl[nb][3]);
                }
            #pragma unroll
            for (int mt = 0; mt < 2; mt++)
                #pragma unroll
                for (int nb = 0; nb < 4; nb++) {
                    mma16(acc[mt][nb * 2 + 0], al[mt], bh[nb][0], bh[nb][2]);
                    mma16(acc[mt][nb * 2 + 1], al[mt], bh[nb][1], bh[nb][3]);
                }
        }
        __syncthreads();
    }
}

// ================= 1-pass GEMM mainloop (hi only, 4 stages) =================
__device__ __forceinline__ void gemm1_main(
    const __half* __restrict__ Ah, int lda,
    const __half* __restrict__ Bh, int ldb,
    int ktot, float (&acc)[2][8][4], char* smem, int tid)
{
    const int wid = tid >> 5, lane = tid & 31;
    const int wm = (wid & 3) * 32, wn = (wid >> 2) * 64;
    const int q = lane >> 3;
    const int lrow = (lane & 7) + (q & 1) * 8;
    const int qc = q >> 1;
    const uint32_t sbase = smem_u32(smem);
    const int NK = ktot / BK;

    int pf = 0;
    #pragma unroll
    for (int s = 0; s < STAGES1 - 1; s++) {
        if (pf < NK) {
            uint32_t sp = sbase + (uint32_t)(pf & (STAGES1 - 1)) * STAGE1_B;
            load_tile(sp, Ah, lda, pf * BK, tid);
            load_tile(sp + OFF1_BH, Bh, ldb, pf * BK, tid);
            CP_COMMIT();
            pf++;
        }
    }

    for (int kb = 0; kb < NK; kb++) {
        CP_WAIT2();
        __syncthreads();
        const uint32_t st = sbase + (uint32_t)(kb & (STAGES1 - 1)) * STAGE1_B;

        if (pf < NK) {
            uint32_t sp = sbase + (uint32_t)(pf & (STAGES1 - 1)) * STAGE1_B;
            load_tile(sp, Ah, lda, pf * BK, tid);
            load_tile(sp + OFF1_BH, Bh, ldb, pf * BK, tid);
            CP_COMMIT();
            pf++;
        } else {
            CP_COMMIT();
        }

        #pragma unroll
        for (int ks = 0; ks < 2; ks++) {
            const int c = 2 * ks + qc;
            uint32_t ah[2][4];
            #pragma unroll
            for (int mt = 0; mt < 2; mt++)
                ldm4(ah[mt], tile_addr(st, wm + mt * 16 + lrow, c));
            uint32_t bh[4][4];
            #pragma unroll
            for (int nb = 0; nb < 4; nb++)
                ldm4(bh[nb], tile_addr(st + OFF1_BH, wn + nb * 16 + lrow, c));
            #pragma unroll
            for (int mt = 0; mt < 2; mt++)
                #pragma unroll
                for (int nb = 0; nb < 4; nb++) {
                    mma16(acc[mt][nb * 2 + 0], ah[mt], bh[nb][0], bh[nb][2]);
                    mma16(acc[mt][nb * 2 + 1], ah[mt], bh[nb][1], bh[nb][3]);
                }
        }
        __syncthreads();
    }
}

__device__ __forceinline__ void split2(float x, float y, __half2& h, __half2& l) {
    __half hx = __float2half_rn(x), hy = __float2half_rn(y);
    h = __halves2half2(hx, hy);
    l = __halves2half2(__float2half_rn(x - __half2float(hx)),
                       __float2half_rn(y - __half2float(hy)));
}

// ================= kernels =================
// X convert
__global__ __launch_bounds__(256) void cvt_x_kernel(const float* __restrict__ src)
{
    int i = blockIdx.x * 256 + threadIdx.x;
    float4 v = ((const float4*)src)[i];
    __half2 h0, l0, h1, l1;
    split2(v.x, v.y, h0, l0);
    split2(v.z, v.w, h1, l1);
    ((__half2*)g_Xh)[i * 2] = h0; ((__half2*)g_Xh)[i * 2 + 1] = h1;
    ((__half2*)g_Xl)[i * 2] = l0; ((__half2*)g_Xl)[i * 2 + 1] = l1;
}
// W convert: grid.z selects q/k/v
__global__ __launch_bounds__(256) void cvt_w_kernel(
    const float* __restrict__ Wq, const float* __restrict__ Wk, const float* __restrict__ Wv)
{
    const float* src = blockIdx.z == 0 ? Wq : (blockIdx.z == 1 ? Wk : Wv);
    __half* h = blockIdx.z == 0 ? g_Wqh : (blockIdx.z == 1 ? g_Wkh : g_Wvh);
    __half* l = blockIdx.z == 0 ? g_Wql : (blockIdx.z == 1 ? g_Wkl : g_Wvl);
    int i = blockIdx.x * 256 + threadIdx.x;
    float4 v = ((const float4*)src)[i];
    __half2 h0, l0, h1, l1;
    split2(v.x, v.y, h0, l0);
    split2(v.z, v.w, h1, l1);
    ((__half2*)h)[i * 2] = h0; ((__half2*)h)[i * 2 + 1] = h1;
    ((__half2*)l)[i * 2] = l0; ((__half2*)l)[i * 2 + 1] = l1;
}

// Q/K projection
__global__ __launch_bounds__(256, 2) void qk_proj_kernel(
    const float* __restrict__ bq, const float* __restrict__ bk)
{
    extern __shared__ char smem[];
    const int tid = threadIdx.x, wid = tid >> 5, lane = tid & 31;
    const int g = lane >> 2, tg = lane & 3;
    const int m0 = blockIdx.y * 128, n0 = blockIdx.x * 128;
    const __half* Wh = blockIdx.z ? g_Wkh : g_Wqh;
    const __half* Wl = blockIdx.z ? g_Wkl : g_Wql;
    const float* bias = blockIdx.z ? bk : bq;
    __half* Oh = blockIdx.z ? g_Kh : g_Qh;
    __half* Ol = blockIdx.z ? g_Kl : g_Ql;

    float acc[2][8][4] = {};
    gemm_main(g_Xh + (size_t)m0 * DIM, g_Xl + (size_t)m0 * DIM, DIM,
              Wh + (size_t)n0 * DIM, Wl + (size_t)n0 * DIM, DIM,
              DIM, acc, smem, tid);

    const int wm = (wid & 3) * 32, wn = (wid >> 2) * 64;
    #pragma unroll
    for (int mt = 0; mt < 2; mt++) {
        int m = m0 + wm + mt * 16 + g;
        #pragma unroll
        for (int nt = 0; nt < 8; nt++) {
            int n = n0 + wn + nt * 8 + tg * 2;
            float b0 = bias[n], b1 = bias[n + 1];
            __half2 h, l;
            split2(acc[mt][nt][0] + b0, acc[mt][nt][1] + b1, h, l);
            *(__half2*)&Oh[(size_t)m * DIM + n] = h;
            *(__half2*)&Ol[(size_t)m * DIM + n] = l;
            split2(acc[mt][nt][2] + b0, acc[mt][nt][3] + b1, h, l);
            *(__half2*)&Oh[(size_t)(m + 8) * DIM + n] = h;
            *(__half2*)&Ol[(size_t)(m + 8) * DIM + n] = l;
        }
    }
}

// V projection transposed -> Vt hi only
__global__ __launch_bounds__(256, 2) void v_proj_kernel(const float* __restrict__ bv)
{
    extern __shared__ char smem[];
    const int tid = threadIdx.x, wid = tid >> 5, lane = tid & 31;
    const int g = lane >> 2, tg = lane & 3;
    const int m0 = blockIdx.y * 128, n0 = blockIdx.x * 128;

    float acc[2][8][4] = {};
    gemm_main(g_Wvh + (size_t)m0 * DIM, g_Wvl + (size_t)m0 * DIM, DIM,
              g_Xh + (size_t)n0 * DIM, g_Xl + (size_t)n0 * DIM, DIM,
              DIM, acc, smem, tid);

    const int wm = (wid & 3) * 32, wn = (wid >> 2) * 64;
    const int b = n0 >> 11;
    #pragma unroll
    for (int mt = 0; mt < 2; mt++) {
        int e = m0 + wm + mt * 16 + g;
        float be0 = bv[e], be1 = bv[e + 8];
        #pragma unroll
        for (int nt = 0; nt < 8; nt++) {
            int t = n0 + wn + nt * 8 + tg * 2;
            int s = t & 2047;
            __half2 h = __halves2half2(__float2half_rn(acc[mt][nt][0] + be0),
                                       __float2half_rn(acc[mt][nt][1] + be0));
            *(__half2*)&g_Vth[((size_t)b * DIM + e) * SEQ + s] = h;
            h = __halves2half2(__float2half_rn(acc[mt][nt][2] + be1),
                               __float2half_rn(acc[mt][nt][3] + be1));
            *(__half2*)&g_Vth[((size_t)b * DIM + e + 8) * SEQ + s] = h;
        }
    }
}

// scores (3-pass, masked, fp32 out)
__global__ __launch_bounds__(256, 2) void scores_kernel(
    const int* __restrict__ mask, float* __restrict__ out_w, float scale)
{
    extern __shared__ char smem[];
    const int tid = threadIdx.x, wid = tid >> 5, lane = tid & 31;
    const int g = lane >> 2, tg = lane & 3;
    const int b = blockIdx.z;
    const int m0 = blockIdx.y * 128, n0 = blockIdx.x * 128;
    const size_t qoff = ((size_t)b * SEQ + m0) * DIM;
    const size_t koff = ((size_t)b * SEQ + n0) * DIM;

    float acc[2][8][4] = {};
    gemm_main(g_Qh + qoff, g_Ql + qoff, DIM, g_Kh + koff, g_Kl + koff, DIM,
              DIM, acc, smem, tid);

    const int wm = (wid & 3) * 32, wn = (wid >> 2) * 64;
    const size_t base = (size_t)b * SEQ * SEQ;
    #pragma unroll
    for (int mt = 0; mt < 2; mt++) {
        int qq = m0 + wm + mt * 16 + g;
        #pragma unroll
        for (int nt = 0; nt < 8; nt++) {
            int n = n0 + wn + nt * 8 + tg * 2;
            size_t i0 = base + (size_t)qq * SEQ + n;
            size_t i1 = base + (size_t)(qq + 8) * SEQ + n;
            int2 mk0 = *(const int2*)&mask[i0];
            int2 mk1 = *(const int2*)&mask[i1];
            *(float2*)&out_w[i0] = make_float2(mk0.x ? acc[mt][nt][0] * scale : -1e9f,
                                              mk0.y ? acc[mt][nt][1] * scale : -1e9f);
            *(float2*)&out_w[i1] = make_float2(mk1.x ? acc[mt][nt][2] * scale : -1e9f,
                                              mk1.y ? acc[mt][nt][3] * scale : -1e9f);
        }
    }
}

// softmax in place (fp32) + fp16 hi copy
__global__ __launch_bounds__(256) void softmax_kernel(
    float* __restrict__ W, __half* __restrict__ Wh)
{
    const size_t rowb = (size_t)blockIdx.x * SEQ;
    float4* p = (float4*)(W + rowb);
    __half2* ph = (__half2*)(Wh + rowb);
    const int tid = threadIdx.x;

    float4 v[2];
    float m = -INFINITY;
    #pragma unroll
    for (int i = 0; i < 2; i++) {
        v[i] = p[tid + i * 256];
        m = fmaxf(m, fmaxf(fmaxf(v[i].x, v[i].y), fmaxf(v[i].z, v[i].w)));
    }
    __shared__ float red[256];
    red[tid] = m; __syncthreads();
    #pragma unroll
    for (int s = 128; s > 0; s >>= 1) { if (tid < s) red[tid] = fmaxf(red[tid], red[tid + s]); __syncthreads(); }
    m = red[0]; __syncthreads();

    float sum = 0.0f;
    #pragma unroll
    for (int i = 0; i < 2; i++) {
        v[i].x = __expf(v[i].x - m); v[i].y = __expf(v[i].y - m);
        v[i].z = __expf(v[i].z - m); v[i].w = __expf(v[i].w - m);
        sum += v[i].x + v[i].y + v[i].z + v[i].w;
    }
    red[tid] = sum; __syncthreads();
    #pragma unroll
    for (int s = 128; s > 0; s >>= 1) { if (tid < s) red[tid] += red[tid + s]; __syncthreads(); }
    float inv = 1.0f / red[0];

    #pragma unroll
    for (int i = 0; i < 2; i++) {
        int j = tid + i * 256;
        v[i].x *= inv; v[i].y *= inv; v[i].z *= inv; v[i].w *= inv;
        p[j] = v[i];
        ph[j * 2]     = __halves2half2(__float2half_rn(v[i].x), __float2half_rn(v[i].y));
        ph[j * 2 + 1] = __halves2half2(__float2half_rn(v[i].z), __float2half_rn(v[i].w));
    }
}

// out (1-pass fp16): C[q][d] = Wgt_h[q]·Vt_h[d]
__global__ __launch_bounds__(256, 2) void out_kernel(float* __restrict__ O)
{
    extern __shared__ char smem[];
    const int tid = threadIdx.x, wid = tid >> 5, lane = tid & 31;
    const int g = lane >> 2, tg = lane & 3;
    const int b = blockIdx.z;
    const int m0 = blockIdx.y * 128, n0 = blockIdx.x * 128;
    const size_t aoff = (size_t)b * SEQ * SEQ + (size_t)m0 * SEQ;
    const size_t boff = (size_t)b * DIM * SEQ + (size_t)n0 * SEQ;

    float acc[2][8][4] = {};
    gemm1_main(g_Wth + aoff, SEQ, g_Vth + boff, SEQ, SEQ, acc, smem, tid);

    const int wm = (wid & 3) * 32, wn = (wid >> 2) * 64;
    float* Ob = O + (size_t)b * SEQ * DIM;
    #pragma unroll
    for (int mt = 0; mt < 2; mt++) {
        int qq = m0 + wm + mt * 16 + g;
        #pragma unroll
        for (int nt = 0; nt < 8; nt++) {
            int n = n0 + wn + nt * 8 + tg * 2;
            *(float2*)&Ob[(size_t)qq * DIM + n] = make_float2(acc[mt][nt][0], acc[mt][nt][1]);
            *(float2*)&Ob[(size_t)(qq + 8) * DIM + n] = make_float2(acc[mt][nt][2], acc[mt][nt][3]);
        }
    }
}

// ================= launch =================
extern "C" void kernel_launch(void* const* d_in, const int* in_sizes, int n_in,
                              void* d_out, int out_size)
{
    const float* X  = (const float*)d_in[0];
    const int*   mk = (const int*)  d_in[1];
    const float* Wq = (const float*)d_in[2];
    const float* bq = (const float*)d_in[3];
    const float* Wk = (const float*)d_in[4];
    const float* bk = (const float*)d_in[5];
    const float* Wv = (const float*)d_in[6];
    const float* bv = (const float*)d_in[7];

    float* out   = (float*)d_out;
    float* out_S = out;                              // [B, S, D]
    float* out_W = out + (size_t)BATCH * SEQ * DIM;  // [B, S, S]
    const float scale = 1.0f / sqrtf((float)DIM);

    cudaFuncSetAttribute(qk_proj_kernel, cudaFuncAttributeMaxDynamicSharedMemorySize, SMEM3_BYTES);
    cudaFuncSetAttribute(v_proj_kernel,  cudaFuncAttributeMaxDynamicSharedMemorySize, SMEM3_BYTES);
    cudaFuncSetAttribute(scores_kernel,  cudaFuncAttributeMaxDynamicSharedMemorySize, SMEM3_BYTES);
    cudaFuncSetAttribute(out_kernel,     cudaFuncAttributeMaxDynamicSharedMemorySize, SMEM1_BYTES);

    __half *wth;
    cudaGetSymbolAddress((void**)&wth, g_Wth);

    cvt_x_kernel<<<MROWS * DIM / 4 / 256, 256>>>(X);
    cvt_w_kernel<<<dim3(DIM * DIM / 4 / 256, 1, 3), 256>>>(Wq, Wk, Wv);

    qk_proj_kernel<<<dim3(4, 128, 2), 256, SMEM3_BYTES>>>(bq, bk);
    v_proj_kernel<<<dim3(128, 4, 1), 256, SMEM3_BYTES>>>(bv);
    scores_kernel<<<dim3(16, 16, 8), 256, SMEM3_BYTES>>>(mk, out_W, scale);
    softmax_kernel<<<BATCH * SEQ, 256>>>(out_W, wth);
    out_kernel<<<dim3(4, 16, 8), 256, SMEM1_BYTES>>>(out_S);
}